// round 1
// baseline (speedup 1.0000x reference)
#include <cuda_runtime.h>
#include <math.h>

#define BB 16
#define LL 512
#define CC 1024
#define NH 8
#define HD 128
#define MM (BB*LL)        // 8192 rows
#define N3 (3*CC)         // 3072

// Scratch (static device globals — no runtime allocation)
__device__ float g_deg[MM];                       // 32 KB
__device__ float g_xg[(size_t)MM*CC];             // 32 MB
__device__ float g_qkv[(size_t)MM*N3];            // 96 MB

__device__ __forceinline__ float sigmoidf(float v) {
    return 1.0f / (1.0f + expf(-v));
}

// ---------------------------------------------------------------------------
// K1: degree[b,l] = sum_m adj[b,l,m]   (warp per row, float4 loads)
// ---------------------------------------------------------------------------
__global__ void degree_kernel(const float* __restrict__ adj) {
    int warp = (blockIdx.x * blockDim.x + threadIdx.x) >> 5;
    int lane = threadIdx.x & 31;
    if (warp >= MM) return;
    const float4* row = (const float4*)(adj + (size_t)warp * LL);  // 128 float4
    float s = 0.0f;
    #pragma unroll
    for (int j = 0; j < 4; j++) {
        float4 v = row[lane + 32*j];
        s += v.x + v.y + v.z + v.w;
    }
    #pragma unroll
    for (int o = 16; o > 0; o >>= 1) s += __shfl_xor_sync(0xffffffffu, s, o);
    if (lane == 0) g_deg[warp] = s;
}

// ---------------------------------------------------------------------------
// K2: xg[b,l,c] = x * sigmoid(degree[b,l]*W_d[c] + b_d[c])
// ---------------------------------------------------------------------------
__global__ void gate_kernel(const float* __restrict__ x,
                            const float* __restrict__ Wd,
                            const float* __restrict__ bd) {
    int i4 = blockIdx.x * blockDim.x + threadIdx.x;   // over MM*CC/4
    int row = i4 >> 8;          // CC/4 = 256 float4 per row
    int c4  = i4 & 255;
    float deg = g_deg[row];
    float4 xv = ((const float4*)x)[i4];
    float4 wv = ((const float4*)Wd)[c4];
    float4 bv = ((const float4*)bd)[c4];
    float4 o;
    o.x = xv.x * sigmoidf(deg*wv.x + bv.x);
    o.y = xv.y * sigmoidf(deg*wv.y + bv.y);
    o.z = xv.z * sigmoidf(deg*wv.z + bv.z);
    o.w = xv.w * sigmoidf(deg*wv.w + bv.w);
    ((float4*)g_xg)[i4] = o;
}

// ---------------------------------------------------------------------------
// K3: SGEMM  qkv[8192,3072] = xg[8192,1024] @ W_qkv[1024,3072] + b_qkv
// 128x128 block tile, BK=8, 256 threads, 8x8 per thread (quad-split layout)
// ---------------------------------------------------------------------------
#define Bb 8
__global__ __launch_bounds__(256) void sgemm_qkv(const float* __restrict__ Bw,
                                                  const float* __restrict__ bias) {
    __shared__ float As[Bb][128];
    __shared__ float Bs[Bb][128];
    int bx = blockIdx.x;   // 24 N-tiles
    int by = blockIdx.y;   // 64 M-tiles
    int tid = threadIdx.x;
    int tx = tid & 15;     // 16 across N
    int ty = tid >> 4;     // 16 across M

    float acc[8][8];
    #pragma unroll
    for (int i = 0; i < 8; i++)
        #pragma unroll
        for (int j = 0; j < 8; j++) acc[i][j] = 0.0f;

    const float* A = g_xg + (size_t)by * 128 * CC;
    const float* Bp = Bw + (size_t)bx * 128;

    int arow = tid >> 1;          // 0..127
    int acol = (tid & 1) * 4;     // 0 or 4
    int brow = tid >> 5;          // 0..7
    int bcol = (tid & 31) * 4;    // 0..124

    for (int k0 = 0; k0 < CC; k0 += Bb) {
        float4 av = *(const float4*)(A + (size_t)arow * CC + k0 + acol);
        As[acol+0][arow] = av.x;
        As[acol+1][arow] = av.y;
        As[acol+2][arow] = av.z;
        As[acol+3][arow] = av.w;
        float4 bv = *(const float4*)(Bp + (size_t)(k0 + brow) * N3 + bcol);
        *(float4*)&Bs[brow][bcol] = bv;
        __syncthreads();

        #pragma unroll
        for (int k = 0; k < Bb; k++) {
            float4 a0 = *(const float4*)&As[k][ty*4];
            float4 a1 = *(const float4*)&As[k][64 + ty*4];
            float4 b0 = *(const float4*)&Bs[k][tx*4];
            float4 b1 = *(const float4*)&Bs[k][64 + tx*4];
            float ra[8] = {a0.x,a0.y,a0.z,a0.w, a1.x,a1.y,a1.z,a1.w};
            float rb[8] = {b0.x,b0.y,b0.z,b0.w, b1.x,b1.y,b1.z,b1.w};
            #pragma unroll
            for (int i = 0; i < 8; i++)
                #pragma unroll
                for (int j = 0; j < 8; j++) acc[i][j] += ra[i] * rb[j];
        }
        __syncthreads();
    }

    // epilogue with bias
    float4 bias0 = *(const float4*)(bias + bx*128 + tx*4);
    float4 bias1 = *(const float4*)(bias + bx*128 + 64 + tx*4);
    #pragma unroll
    for (int i = 0; i < 8; i++) {
        int gm = by*128 + ((i < 4) ? (ty*4 + i) : (64 + ty*4 + i - 4));
        float* dst = g_qkv + (size_t)gm * N3 + bx*128;
        float4 o0, o1;
        o0.x = acc[i][0] + bias0.x; o0.y = acc[i][1] + bias0.y;
        o0.z = acc[i][2] + bias0.z; o0.w = acc[i][3] + bias0.w;
        o1.x = acc[i][4] + bias1.x; o1.y = acc[i][5] + bias1.y;
        o1.z = acc[i][6] + bias1.z; o1.w = acc[i][7] + bias1.w;
        *(float4*)(dst + tx*4)      = o0;
        *(float4*)(dst + 64 + tx*4) = o1;
    }
}

// ---------------------------------------------------------------------------
// K4: attention. One-pass: acc += s*V, denom += s, divide at end.
// Block = (b,h) x 16 query rows; warp per query row; 128-key smem chunks.
// s = dot(sig(qk_q), sig(qk_m)) / sqrt(128) only where adj != 0.
// out = relu(acc/(denom+1e-6) + res)
// ---------------------------------------------------------------------------
__global__ __launch_bounds__(512) void attn_kernel(const float* __restrict__ adj,
                                                    float* __restrict__ out) {
    extern __shared__ float sm[];
    float* Ks = sm;                 // 128 keys x 128 d (post-sigmoid)
    float* Vs = sm + 128*128;       // 128 keys x 128 d

    int bh = blockIdx.x;            // 0..127
    int rt = blockIdx.y;            // 0..31
    int b = bh >> 3, h = bh & 7;
    int warp = threadIdx.x >> 5, lane = threadIdx.x & 31;
    int r = rt * 16 + warp;         // query row 0..511

    size_t qbase = ((size_t)(b*LL + r)) * N3 + h*HD;
    float4 q = *(const float4*)(g_qkv + qbase + lane*4);
    q.x = sigmoidf(q.x); q.y = sigmoidf(q.y);
    q.z = sigmoidf(q.z); q.w = sigmoidf(q.w);

    float4 acc = make_float4(0.f, 0.f, 0.f, 0.f);
    float denom = 0.0f;
    const float* adjrow = adj + ((size_t)b*LL + r) * LL;
    const float scale = 0.08838834764831845f;   // 1/sqrt(128)

    for (int c0 = 0; c0 < LL; c0 += 128) {
        // cooperative load of key/value chunk (coalesced float4)
        for (int t = threadIdx.x; t < 128*32; t += blockDim.x) {
            int m = t >> 5;
            int d4 = t & 31;
            size_t krow = ((size_t)(b*LL + c0 + m)) * N3 + h*HD;
            float4 kv = *(const float4*)(g_qkv + krow + d4*4);
            kv.x = sigmoidf(kv.x); kv.y = sigmoidf(kv.y);
            kv.z = sigmoidf(kv.z); kv.w = sigmoidf(kv.w);
            ((float4*)Ks)[t] = kv;
            ((float4*)Vs)[t] = *(const float4*)(g_qkv + krow + 2*CC + d4*4);
        }
        __syncthreads();

        for (int m = 0; m < 128; m++) {
            float a = adjrow[c0 + m];        // uniform across warp
            if (a != 0.0f) {
                float4 kk = ((const float4*)Ks)[m*32 + lane];
                float p = q.x*kk.x + q.y*kk.y + q.z*kk.z + q.w*kk.w;
                #pragma unroll
                for (int o = 16; o > 0; o >>= 1)
                    p += __shfl_xor_sync(0xffffffffu, p, o);
                float s = p * scale;
                denom += s;
                float4 vv = ((const float4*)Vs)[m*32 + lane];
                acc.x += s * vv.x; acc.y += s * vv.y;
                acc.z += s * vv.z; acc.w += s * vv.w;
            }
        }
        __syncthreads();
    }

    float inv = 1.0f / (denom + 1e-6f);
    float4 res = *(const float4*)(g_qkv + qbase + CC + lane*4);
    float4 o;
    o.x = fmaxf(acc.x*inv + res.x, 0.0f);
    o.y = fmaxf(acc.y*inv + res.y, 0.0f);
    o.z = fmaxf(acc.z*inv + res.z, 0.0f);
    o.w = fmaxf(acc.w*inv + res.w, 0.0f);
    *(float4*)(out + ((size_t)(b*LL + r)) * CC + h*HD + lane*4) = o;
}

// ---------------------------------------------------------------------------
extern "C" void kernel_launch(void* const* d_in, const int* in_sizes, int n_in,
                              void* d_out, int out_size) {
    const float* x    = (const float*)d_in[0];   // [16,512,1024]
    const float* adj  = (const float*)d_in[1];   // [16,512,512]
    const float* Wqkv = (const float*)d_in[2];   // [1024,3072]
    const float* bqkv = (const float*)d_in[3];   // [3072]
    const float* Wd   = (const float*)d_in[4];   // [1,1024]
    const float* bd   = (const float*)d_in[5];   // [1024]
    float* out = (float*)d_out;                  // [16,512,1024]

    // K1: degree (warp per row)
    degree_kernel<<<MM/8, 256>>>(adj);
    // K2: gated input
    gate_kernel<<<(MM*CC/4)/256, 256>>>(x, Wd, bd);
    // K3: fused QKV projection
    sgemm_qkv<<<dim3(N3/128, MM/128), 256>>>(Wqkv, bqkv);
    // K4: attention (128 KB dynamic smem)
    static bool attr_set = false;
    if (!attr_set) {
        cudaFuncSetAttribute(attn_kernel,
                             cudaFuncAttributeMaxDynamicSharedMemorySize,
                             2*128*128*sizeof(float));
        attr_set = true;
    }
    attn_kernel<<<dim3(NH*BB, LL/16), 512, 2*128*128*sizeof(float)>>>(adj, out);
}

// round 2
// speedup vs baseline: 2.1628x; 2.1628x over previous
#include <cuda_runtime.h>
#include <math.h>

#define BB 16
#define LL 512
#define CC 1024
#define NH 8
#define HD 128
#define MM (BB*LL)        // 8192 rows
#define N3 (3*CC)         // 3072

// Scratch (static device globals — no runtime allocation)
__device__ float g_deg[MM];                       // 32 KB
__device__ float g_xg[(size_t)MM*CC];             // 32 MB
__device__ float g_qkv[(size_t)MM*N3];            // 96 MB (sig(qk) | res | value)

__device__ __forceinline__ float sigmoidf(float v) {
    return 1.0f / (1.0f + expf(-v));
}

// packed f32x2 helpers (Blackwell sm_100+: fma.rn.f32x2)
__device__ __forceinline__ unsigned long long pk(float lo, float hi) {
    unsigned long long r;
    asm("mov.b64 %0, {%1,%2};" : "=l"(r) : "f"(lo), "f"(hi));
    return r;
}
__device__ __forceinline__ void upk(unsigned long long v, float& lo, float& hi) {
    asm("mov.b64 {%0,%1}, %2;" : "=f"(lo), "=f"(hi) : "l"(v));
}
__device__ __forceinline__ void ffma2(unsigned long long& d,
                                      unsigned long long a,
                                      unsigned long long b) {
    asm("fma.rn.f32x2 %0, %1, %2, %0;" : "+l"(d) : "l"(a), "l"(b));
}

// ---------------------------------------------------------------------------
// K1: degree[b,l] = sum_m adj[b,l,m]
// ---------------------------------------------------------------------------
__global__ void degree_kernel(const float* __restrict__ adj) {
    int warp = (blockIdx.x * blockDim.x + threadIdx.x) >> 5;
    int lane = threadIdx.x & 31;
    if (warp >= MM) return;
    const float4* row = (const float4*)(adj + (size_t)warp * LL);
    float s = 0.0f;
    #pragma unroll
    for (int j = 0; j < 4; j++) {
        float4 v = row[lane + 32*j];
        s += v.x + v.y + v.z + v.w;
    }
    #pragma unroll
    for (int o = 16; o > 0; o >>= 1) s += __shfl_xor_sync(0xffffffffu, s, o);
    if (lane == 0) g_deg[warp] = s;
}

// ---------------------------------------------------------------------------
// K2: xg = x * sigmoid(deg*W_d + b_d)
// ---------------------------------------------------------------------------
__global__ void gate_kernel(const float* __restrict__ x,
                            const float* __restrict__ Wd,
                            const float* __restrict__ bd) {
    int i4 = blockIdx.x * blockDim.x + threadIdx.x;
    int row = i4 >> 8;
    int c4  = i4 & 255;
    float deg = g_deg[row];
    float4 xv = ((const float4*)x)[i4];
    float4 wv = ((const float4*)Wd)[c4];
    float4 bv = ((const float4*)bd)[c4];
    float4 o;
    o.x = xv.x * sigmoidf(deg*wv.x + bv.x);
    o.y = xv.y * sigmoidf(deg*wv.y + bv.y);
    o.z = xv.z * sigmoidf(deg*wv.z + bv.z);
    o.w = xv.w * sigmoidf(deg*wv.w + bv.w);
    ((float4*)g_xg)[i4] = o;
}

// ---------------------------------------------------------------------------
// K3: SGEMM  qkv[8192,3072] = xg @ W_qkv + b_qkv, sigmoid fused on qk third.
// 128x128x8 tile, double-buffered smem, fma.rn.f32x2 inner loop.
// ---------------------------------------------------------------------------
__global__ __launch_bounds__(256) void sgemm_qkv(const float* __restrict__ Bw,
                                                 const float* __restrict__ bias) {
    __shared__ float As[2][8][128];
    __shared__ float Bs[2][8][128];
    int bx = blockIdx.x;   // 24 N-tiles
    int by = blockIdx.y;   // 64 M-tiles
    int tid = threadIdx.x;
    int tx = tid & 15;
    int ty = tid >> 4;

    const float* A  = g_xg + (size_t)by * 128 * CC;
    const float* Bp = Bw + (size_t)bx * 128;

    int arow = tid >> 1;
    int acol = (tid & 1) * 4;
    int brow = tid >> 5;
    int bcol = (tid & 31) * 4;

    unsigned long long acc[8][4];
    #pragma unroll
    for (int i = 0; i < 8; i++)
        #pragma unroll
        for (int j = 0; j < 4; j++) acc[i][j] = 0ULL;

    float4 av = *(const float4*)(A + (size_t)arow * CC + acol);
    float4 bv = *(const float4*)(Bp + (size_t)brow * N3 + bcol);
    As[0][acol+0][arow] = av.x;
    As[0][acol+1][arow] = av.y;
    As[0][acol+2][arow] = av.z;
    As[0][acol+3][arow] = av.w;
    *(float4*)&Bs[0][brow][bcol] = bv;
    __syncthreads();

    for (int it = 0; it < 128; it++) {
        int p = it & 1;
        if (it < 127) {
            int k0 = (it + 1) * 8;
            av = *(const float4*)(A + (size_t)arow * CC + k0 + acol);
            bv = *(const float4*)(Bp + (size_t)(k0 + brow) * N3 + bcol);
        }
        #pragma unroll
        for (int k = 0; k < 8; k++) {
            float4 a0 = *(const float4*)&As[p][k][ty*4];
            float4 a1 = *(const float4*)&As[p][k][64 + ty*4];
            float4 b0 = *(const float4*)&Bs[p][k][tx*4];
            float4 b1 = *(const float4*)&Bs[p][k][64 + tx*4];
            unsigned long long rb[4] = {pk(b0.x,b0.y), pk(b0.z,b0.w),
                                        pk(b1.x,b1.y), pk(b1.z,b1.w)};
            float ra[8] = {a0.x,a0.y,a0.z,a0.w, a1.x,a1.y,a1.z,a1.w};
            #pragma unroll
            for (int i = 0; i < 8; i++) {
                unsigned long long ra2 = pk(ra[i], ra[i]);
                #pragma unroll
                for (int j = 0; j < 4; j++) ffma2(acc[i][j], ra2, rb[j]);
            }
        }
        if (it < 127) {
            As[p^1][acol+0][arow] = av.x;
            As[p^1][acol+1][arow] = av.y;
            As[p^1][acol+2][arow] = av.z;
            As[p^1][acol+3][arow] = av.w;
            *(float4*)&Bs[p^1][brow][bcol] = bv;
            __syncthreads();
        }
    }

    float4 bias0 = *(const float4*)(bias + bx*128 + tx*4);
    float4 bias1 = *(const float4*)(bias + bx*128 + 64 + tx*4);
    bool do_sig = (bx < 8);   // qk third gets sigmoid fused
    #pragma unroll
    for (int i = 0; i < 8; i++) {
        int gm = by*128 + ((i < 4) ? (ty*4 + i) : (64 + ty*4 + i - 4));
        float* dst = g_qkv + (size_t)gm * N3 + bx*128;
        float o[8];
        upk(acc[i][0], o[0], o[1]);
        upk(acc[i][1], o[2], o[3]);
        upk(acc[i][2], o[4], o[5]);
        upk(acc[i][3], o[6], o[7]);
        o[0]+=bias0.x; o[1]+=bias0.y; o[2]+=bias0.z; o[3]+=bias0.w;
        o[4]+=bias1.x; o[5]+=bias1.y; o[6]+=bias1.z; o[7]+=bias1.w;
        if (do_sig) {
            #pragma unroll
            for (int j = 0; j < 8; j++) o[j] = sigmoidf(o[j]);
        }
        *(float4*)(dst + tx*4)      = make_float4(o[0],o[1],o[2],o[3]);
        *(float4*)(dst + 64 + tx*4) = make_float4(o[4],o[5],o[6],o[7]);
    }
}

// ---------------------------------------------------------------------------
// K4: attention v2 — two-phase register-tiled GEMM, no shuffles.
//   Per block: 64 query rows of one (b,h); loop 64-key chunks.
//   Phase 1: S[64,64] = Qs·Ks^T * scale, adj-masked, written to smem.
//   Phase 2: O[64,128] += S·Vs (f32x2), denom[r] += rowsum(S).
//   Epilogue: relu(O/denom + res).
// ---------------------------------------------------------------------------
#define QS_STR 129
#define VS_STR 132
#define SS_STR 65
#define ATTN_SMEM ((64*QS_STR*2 + 64*VS_STR + 64*SS_STR + 64) * 4)

__global__ __launch_bounds__(256) void attn2_kernel(const float* __restrict__ adj,
                                                    float* __restrict__ out) {
    extern __shared__ float sm[];
    float* Qs   = sm;                     // [64][129] sig(qk) rows
    float* Ks   = Qs + 64*QS_STR;         // [64][129] sig(qk) keys
    float* Vs   = Ks + 64*QS_STR;         // [64][132] values
    float* Ssm  = Vs + 64*VS_STR;         // [64][65]  adj tile then masked S
    float* dsum = Ssm + 64*SS_STR;        // [64]

    int rt = blockIdx.x;                  // 0..7 row tile (fast → K/V L2 reuse)
    int bh = blockIdx.y;                  // 0..127
    int b = bh >> 3, h = bh & 7;
    int t = threadIdx.x;
    int r0 = rt * 64;

    const float* qbase = g_qkv + ((size_t)(b*LL + r0)) * N3 + h*HD;

    // load Q tile (sigmoid pre-applied by sgemm epilogue)
    for (int p = t; p < 64*32; p += 256) {
        int row = p >> 5, d4 = p & 31;
        float4 v = *(const float4*)(qbase + (size_t)row * N3 + d4*4);
        float* dst = Qs + row*QS_STR + d4*4;
        dst[0]=v.x; dst[1]=v.y; dst[2]=v.z; dst[3]=v.w;
    }
    if (t < 64) dsum[t] = 0.0f;

    int rg = t >> 4;   // 0..15 : S rows rg*4..+3, O rows rg*4..+3
    int cg = t & 15;   // S cols cg*4..+3, O cols cg*8..+7

    unsigned long long oacc[4][4];
    #pragma unroll
    for (int i = 0; i < 4; i++)
        #pragma unroll
        for (int u = 0; u < 4; u++) oacc[i][u] = 0ULL;

    __syncthreads();

    const float scale = 0.08838834764831845f;   // 1/sqrt(128)
    const float* adjbase = adj + ((size_t)b*LL + r0) * LL;

    for (int c0 = 0; c0 < LL; c0 += 64) {
        // load K chunk (sigmoided), V chunk, adj tile (into Ssm)
        const float* kbase = g_qkv + ((size_t)(b*LL + c0)) * N3 + h*HD;
        for (int p = t; p < 64*32; p += 256) {
            int row = p >> 5, d4 = p & 31;
            const float* src = kbase + (size_t)row * N3 + d4*4;
            float4 kv = *(const float4*)src;
            float* kd = Ks + row*QS_STR + d4*4;
            kd[0]=kv.x; kd[1]=kv.y; kd[2]=kv.z; kd[3]=kv.w;
            *(float4*)(Vs + row*VS_STR + d4*4) = *(const float4*)(src + 2*CC);
        }
        for (int p = t; p < 64*16; p += 256) {
            int row = p >> 4, c4 = p & 15;
            float4 a = *(const float4*)(adjbase + (size_t)row * LL + c0 + c4*4);
            float* ad = Ssm + row*SS_STR + c4*4;
            ad[0]=a.x; ad[1]=a.y; ad[2]=a.z; ad[3]=a.w;
        }
        __syncthreads();

        // phase 1: scores
        float sacc[4][4];
        #pragma unroll
        for (int i = 0; i < 4; i++)
            #pragma unroll
            for (int j = 0; j < 4; j++) sacc[i][j] = 0.0f;
        for (int k = 0; k < HD; k++) {
            float qa[4], kb[4];
            #pragma unroll
            for (int i = 0; i < 4; i++) qa[i] = Qs[(rg*4+i)*QS_STR + k];
            #pragma unroll
            for (int j = 0; j < 4; j++) kb[j] = Ks[(cg*4+j)*QS_STR + k];
            #pragma unroll
            for (int i = 0; i < 4; i++)
                #pragma unroll
                for (int j = 0; j < 4; j++) sacc[i][j] += qa[i]*kb[j];
        }
        // mask with adj (each thread owns its 16 cells exclusively)
        #pragma unroll
        for (int i = 0; i < 4; i++)
            #pragma unroll
            for (int j = 0; j < 4; j++) {
                float* cell = Ssm + (rg*4+i)*SS_STR + (cg*4+j);
                float a = *cell;
                *cell = (a != 0.0f) ? sacc[i][j]*scale : 0.0f;
            }
        __syncthreads();

        // denom accumulation (64 threads, one row each)
        if (t < 64) {
            const float* row = Ssm + t*SS_STR;
            float s = 0.0f;
            #pragma unroll
            for (int c = 0; c < 64; c++) s += row[c];
            dsum[t] += s;
        }

        // phase 2: O += S · V  (f32x2)
        for (int k = 0; k < 64; k++) {
            float4 va = *(const float4*)(Vs + k*VS_STR + cg*8);
            float4 vb = *(const float4*)(Vs + k*VS_STR + cg*8 + 4);
            unsigned long long v2[4] = {pk(va.x,va.y), pk(va.z,va.w),
                                        pk(vb.x,vb.y), pk(vb.z,vb.w)};
            #pragma unroll
            for (int i = 0; i < 4; i++) {
                float s = Ssm[(rg*4+i)*SS_STR + k];
                unsigned long long s2 = pk(s, s);
                #pragma unroll
                for (int u = 0; u < 4; u++) ffma2(oacc[i][u], s2, v2[u]);
            }
        }
        __syncthreads();
    }

    // epilogue: relu(O/denom + res)
    #pragma unroll
    for (int i = 0; i < 4; i++) {
        int row = rg*4 + i;
        float inv = 1.0f / (dsum[row] + 1e-6f);
        const float* resp = g_qkv + ((size_t)(b*LL + r0 + row)) * N3 + CC + h*HD + cg*8;
        float4 rA = *(const float4*)resp;
        float4 rB = *(const float4*)(resp + 4);
        float o[8];
        upk(oacc[i][0], o[0], o[1]);
        upk(oacc[i][1], o[2], o[3]);
        upk(oacc[i][2], o[4], o[5]);
        upk(oacc[i][3], o[6], o[7]);
        float* dst = out + ((size_t)(b*LL + r0 + row)) * CC + h*HD + cg*8;
        *(float4*)dst = make_float4(
            fmaxf(o[0]*inv + rA.x, 0.0f), fmaxf(o[1]*inv + rA.y, 0.0f),
            fmaxf(o[2]*inv + rA.z, 0.0f), fmaxf(o[3]*inv + rA.w, 0.0f));
        *(float4*)(dst + 4) = make_float4(
            fmaxf(o[4]*inv + rB.x, 0.0f), fmaxf(o[5]*inv + rB.y, 0.0f),
            fmaxf(o[6]*inv + rB.z, 0.0f), fmaxf(o[7]*inv + rB.w, 0.0f));
    }
}

// ---------------------------------------------------------------------------
extern "C" void kernel_launch(void* const* d_in, const int* in_sizes, int n_in,
                              void* d_out, int out_size) {
    const float* x    = (const float*)d_in[0];
    const float* adj  = (const float*)d_in[1];
    const float* Wqkv = (const float*)d_in[2];
    const float* bqkv = (const float*)d_in[3];
    const float* Wd   = (const float*)d_in[4];
    const float* bd   = (const float*)d_in[5];
    float* out = (float*)d_out;

    cudaFuncSetAttribute(attn2_kernel,
                         cudaFuncAttributeMaxDynamicSharedMemorySize, ATTN_SMEM);

    degree_kernel<<<MM/8, 256>>>(adj);
    gate_kernel<<<(MM*CC/4)/256, 256>>>(x, Wd, bd);
    sgemm_qkv<<<dim3(N3/128, MM/128), 256>>>(Wqkv, bqkv);
    attn2_kernel<<<dim3(LL/64, NH*BB), 256, ATTN_SMEM>>>(adj, out);
}

// round 4
// speedup vs baseline: 2.7722x; 1.2818x over previous
#include <cuda_runtime.h>
#include <cuda_bf16.h>
#include <math.h>
#include <stdint.h>

#define BB 16
#define LL 512
#define CC 1024
#define NH 8
#define HD 128
#define MM (BB*LL)        // 8192 rows
#define N3 (3*CC)         // 3072

// Scratch (static device globals — no runtime allocation)
__device__ float g_deg[MM];
__device__ __nv_bfloat16 g_a_hi[(size_t)MM*CC];   // gated x, bf16 hi   16MB
__device__ __nv_bfloat16 g_a_lo[(size_t)MM*CC];   // gated x, bf16 lo   16MB
__device__ __nv_bfloat16 g_w_hi[(size_t)N3*CC];   // W^T [3072,1024] hi  6MB
__device__ __nv_bfloat16 g_w_lo[(size_t)N3*CC];   // W^T lo              6MB
__device__ float g_qkv[(size_t)MM*N3];            // sig(qk) | res | val 96MB

__device__ __forceinline__ float sigmoidf(float v) {
    return 1.0f / (1.0f + expf(-v));
}

// ---------------- packed f32x2 helpers (attention) ----------------
__device__ __forceinline__ unsigned long long pk(float lo, float hi) {
    unsigned long long r;
    asm("mov.b64 %0, {%1,%2};" : "=l"(r) : "f"(lo), "f"(hi));
    return r;
}
__device__ __forceinline__ void upk(unsigned long long v, float& lo, float& hi) {
    asm("mov.b64 {%0,%1}, %2;" : "=f"(lo), "=f"(hi) : "l"(v));
}
__device__ __forceinline__ void ffma2(unsigned long long& d,
                                      unsigned long long a,
                                      unsigned long long b) {
    asm("fma.rn.f32x2 %0, %1, %2, %0;" : "+l"(d) : "l"(a), "l"(b));
}

// ---------------- mma / async helpers (plain sm_80+ features) ----------------
__device__ __forceinline__ uint32_t smem_u32(const void* p) {
    return (uint32_t)__cvta_generic_to_shared((void*)p);
}
__device__ __forceinline__ void cp16(uint32_t dst, const void* src) {
    asm volatile("cp.async.cg.shared.global [%0], [%1], 16;" :: "r"(dst), "l"(src));
}
__device__ __forceinline__ void cp_commit() {
    asm volatile("cp.async.commit_group;" ::: "memory");
}
template<int N> __device__ __forceinline__ void cp_wait() {
    asm volatile("cp.async.wait_group %0;" :: "n"(N) : "memory");
}
__device__ __forceinline__ void ldm4(uint32_t* r, uint32_t addr) {
    asm volatile("ldmatrix.sync.aligned.m8n8.x4.shared.b16 {%0,%1,%2,%3},[%4];"
        : "=r"(r[0]), "=r"(r[1]), "=r"(r[2]), "=r"(r[3]) : "r"(addr));
}
__device__ __forceinline__ void mma16816(float* d, const uint32_t* a, const uint32_t* b) {
    asm volatile("mma.sync.aligned.m16n8k16.row.col.f32.bf16.bf16.f32 "
        "{%0,%1,%2,%3},{%4,%5,%6,%7},{%8,%9},{%0,%1,%2,%3};"
        : "+f"(d[0]), "+f"(d[1]), "+f"(d[2]), "+f"(d[3])
        : "r"(a[0]), "r"(a[1]), "r"(a[2]), "r"(a[3]), "r"(b[0]), "r"(b[1]));
}

// ---------------------------------------------------------------------------
// K1: degree[b,l] = sum_m adj[b,l,m]
// ---------------------------------------------------------------------------
__global__ void degree_kernel(const float* __restrict__ adj) {
    int warp = (blockIdx.x * blockDim.x + threadIdx.x) >> 5;
    int lane = threadIdx.x & 31;
    if (warp >= MM) return;
    const float4* row = (const float4*)(adj + (size_t)warp * LL);
    float s = 0.0f;
    #pragma unroll
    for (int j = 0; j < 4; j++) {
        float4 v = row[lane + 32*j];
        s += v.x + v.y + v.z + v.w;
    }
    #pragma unroll
    for (int o = 16; o > 0; o >>= 1) s += __shfl_xor_sync(0xffffffffu, s, o);
    if (lane == 0) g_deg[warp] = s;
}

// ---------------------------------------------------------------------------
// K2: gated x -> bf16 hi/lo split
// ---------------------------------------------------------------------------
__global__ void gate_kernel(const float* __restrict__ x,
                            const float* __restrict__ Wd,
                            const float* __restrict__ bd) {
    int i4 = blockIdx.x * blockDim.x + threadIdx.x;
    int row = i4 >> 8;
    int c4  = i4 & 255;
    float deg = g_deg[row];
    float4 xv = ((const float4*)x)[i4];
    float4 wv = ((const float4*)Wd)[c4];
    float4 bv = ((const float4*)bd)[c4];
    float v[4];
    v[0] = xv.x * sigmoidf(deg*wv.x + bv.x);
    v[1] = xv.y * sigmoidf(deg*wv.y + bv.y);
    v[2] = xv.z * sigmoidf(deg*wv.z + bv.z);
    v[3] = xv.w * sigmoidf(deg*wv.w + bv.w);
    __nv_bfloat16 h[4], l[4];
    #pragma unroll
    for (int j = 0; j < 4; j++) {
        h[j] = __float2bfloat16(v[j]);
        l[j] = __float2bfloat16(v[j] - __bfloat162float(h[j]));
    }
    *(uint2*)&g_a_hi[(size_t)i4*4] = *(uint2*)h;
    *(uint2*)&g_a_lo[(size_t)i4*4] = *(uint2*)l;
}

// ---------------------------------------------------------------------------
// K2b: W[1024,3072] -> W^T[3072,1024] bf16 hi/lo
// ---------------------------------------------------------------------------
__global__ void wprep_kernel(const float* __restrict__ W) {
    __shared__ float t[32][33];
    int n0 = blockIdx.x * 32;
    int k0 = blockIdx.y * 32;
    int tx = threadIdx.x, ty = threadIdx.y;   // (32, 8)
    #pragma unroll
    for (int i = ty; i < 32; i += 8)
        t[i][tx] = W[(size_t)(k0 + i) * N3 + n0 + tx];
    __syncthreads();
    #pragma unroll
    for (int i = ty; i < 32; i += 8) {
        float v = t[tx][i];
        __nv_bfloat16 h = __float2bfloat16(v);
        __nv_bfloat16 l = __float2bfloat16(v - __bfloat162float(h));
        size_t idx = (size_t)(n0 + i) * CC + k0 + tx;
        g_w_hi[idx] = h;
        g_w_lo[idx] = l;
    }
}

// ---------------------------------------------------------------------------
// K3: HMMA bf16-split GEMM  qkv = A(hi+lo) @ W^T(hi+lo) + bias
// 128x128 tile, K-chunk 32, cp.async double-buffer, mma.sync m16n8k16.
// smem rows padded to 80B -> conflict-free ldmatrix (8 rows on disjoint
// 4-word bank spans).
// ---------------------------------------------------------------------------
#define ROWB 80                      // bytes per smem row (32 bf16 + pad)
#define TILE (128*ROWB)              // 10240 B
#define STAGE (4*TILE)               // Ah|Al|Bh|Bl = 40960 B
#define SG_SMEM (2*STAGE)            // 80 KB

__global__ __launch_bounds__(256) void sgemm_mma(const float* __restrict__ bias) {
    extern __shared__ char sm[];
    uint32_t smb = smem_u32(sm);
    int tid = threadIdx.x, wid = tid >> 5, lane = tid & 31;
    int bx = blockIdx.x, by = blockIdx.y;
    int wm = wid & 3;        // 4 warps along M (32 rows each)
    int wn = wid >> 2;       // 2 warps along N (64 cols each)

    const __nv_bfloat16* Ah = g_a_hi + (size_t)by * 128 * CC;
    const __nv_bfloat16* Al = g_a_lo + (size_t)by * 128 * CC;
    const __nv_bfloat16* Bh = g_w_hi + (size_t)bx * 128 * CC;
    const __nv_bfloat16* Bl = g_w_lo + (size_t)bx * 128 * CC;

    float acc[2][8][4];
    #pragma unroll
    for (int t = 0; t < 2; t++)
        #pragma unroll
        for (int j = 0; j < 8; j++)
            #pragma unroll
            for (int u = 0; u < 4; u++) acc[t][j][u] = 0.0f;

    // loader: chunk = 128 rows x 4 segs(16B) per tile, 4 tiles
    auto load_chunk = [&](int stage, int k0) {
        uint32_t base = smb + stage * STAGE;
        #pragma unroll
        for (int q = 0; q < 2; q++) {
            int c = tid + 256 * q;
            int row = c >> 2, s = c & 3;
            uint32_t off = (uint32_t)(row * ROWB + s * 16);
            size_t go = (size_t)row * CC + k0 + s * 8;
            cp16(base + off,            Ah + go);
            cp16(base + TILE + off,     Al + go);
            cp16(base + 2*TILE + off,   Bh + go);
            cp16(base + 3*TILE + off,   Bl + go);
        }
        cp_commit();
    };

    // per-lane ldmatrix address pieces
    int li = lane >> 3, lr = lane & 7;
    // A: matrix i -> m-sub = (i&1)*8, k-seg = i>>1
    int a_row = wm * 32 + (li & 1) * 8 + lr;
    int a_seg = li >> 1;
    // B: matrix i -> n-sub = (i>>1)*8, k-seg = i&1
    int b_rowbase = wn * 64 + (li >> 1) * 8 + lr;
    int b_seg = li & 1;

    load_chunk(0, 0);

    #pragma unroll 1
    for (int i = 0; i < 32; i++) {
        cp_wait<0>();
        __syncthreads();
        if (i < 31) load_chunk((i + 1) & 1, (i + 1) * 32);

        uint32_t sb = smb + (i & 1) * STAGE;
        #pragma unroll
        for (int ks = 0; ks < 2; ks++) {
            uint32_t ah[2][4], al[2][4];
            #pragma unroll
            for (int t = 0; t < 2; t++) {
                uint32_t aoff = (uint32_t)((a_row + t*16) * ROWB + (ks*2 + a_seg) * 16);
                ldm4(ah[t], sb + aoff);
                ldm4(al[t], sb + TILE + aoff);
            }
            #pragma unroll
            for (int half = 0; half < 2; half++) {
                uint32_t bh[2][4], bl[2][4];
                #pragma unroll
                for (int bt = 0; bt < 2; bt++) {
                    uint32_t boff = (uint32_t)((b_rowbase + half*32 + bt*16) * ROWB
                                               + (ks*2 + b_seg) * 16);
                    ldm4(bh[bt], sb + 2*TILE + boff);
                    ldm4(bl[bt], sb + 3*TILE + boff);
                }
                #pragma unroll
                for (int t = 0; t < 2; t++) {
                    #pragma unroll
                    for (int j = 0; j < 4; j++) {
                        int jj = half * 4 + j;
                        const uint32_t* bhp = &bh[j >> 1][(j & 1) * 2];
                        const uint32_t* blp = &bl[j >> 1][(j & 1) * 2];
                        mma16816(acc[t][jj], ah[t], bhp);
                        mma16816(acc[t][jj], ah[t], blp);
                        mma16816(acc[t][jj], al[t], bhp);
                    }
                }
            }
        }
    }

    // epilogue: bias (+ sigmoid for qk third), direct stores
    bool do_sig = (bx < 8);
    int nb = bx * 128 + wn * 64 + (lane & 3) * 2;
    float2 bj[8];
    #pragma unroll
    for (int j = 0; j < 8; j++) bj[j] = *(const float2*)(bias + nb + j * 8);
    #pragma unroll
    for (int t = 0; t < 2; t++) {
        int gm0 = by * 128 + wm * 32 + t * 16 + (lane >> 2);
        float* d0 = g_qkv + (size_t)gm0 * N3 + nb;
        float* d1 = g_qkv + (size_t)(gm0 + 8) * N3 + nb;
        #pragma unroll
        for (int j = 0; j < 8; j++) {
            float2 lo, hi;
            lo.x = acc[t][j][0] + bj[j].x;
            lo.y = acc[t][j][1] + bj[j].y;
            hi.x = acc[t][j][2] + bj[j].x;
            hi.y = acc[t][j][3] + bj[j].y;
            if (do_sig) {
                lo.x = sigmoidf(lo.x); lo.y = sigmoidf(lo.y);
                hi.x = sigmoidf(hi.x); hi.y = sigmoidf(hi.y);
            }
            *(float2*)(d0 + j*8) = lo;
            *(float2*)(d1 + j*8) = hi;
        }
    }
}

// ---------------------------------------------------------------------------
// K4: attention (unchanged from round 2; 831us, SIMT f32x2)
// ---------------------------------------------------------------------------
#define QS_STR 129
#define VS_STR 132
#define SS_STR 65
#define ATTN_SMEM ((64*QS_STR*2 + 64*VS_STR + 64*SS_STR + 64) * 4)

__global__ __launch_bounds__(256) void attn2_kernel(const float* __restrict__ adj,
                                                    float* __restrict__ out) {
    extern __shared__ float smf[];
    float* Qs   = smf;
    float* Ks   = Qs + 64*QS_STR;
    float* Vs   = Ks + 64*QS_STR;
    float* Ssm  = Vs + 64*VS_STR;
    float* dsum = Ssm + 64*SS_STR;

    int rt = blockIdx.x;
    int bh = blockIdx.y;
    int b = bh >> 3, h = bh & 7;
    int t = threadIdx.x;
    int r0 = rt * 64;

    const float* qbase = g_qkv + ((size_t)(b*LL + r0)) * N3 + h*HD;

    for (int p = t; p < 64*32; p += 256) {
        int row = p >> 5, d4 = p & 31;
        float4 v = *(const float4*)(qbase + (size_t)row * N3 + d4*4);
        float* dst = Qs + row*QS_STR + d4*4;
        dst[0]=v.x; dst[1]=v.y; dst[2]=v.z; dst[3]=v.w;
    }
    if (t < 64) dsum[t] = 0.0f;

    int rg = t >> 4;
    int cg = t & 15;

    unsigned long long oacc[4][4];
    #pragma unroll
    for (int i = 0; i < 4; i++)
        #pragma unroll
        for (int u = 0; u < 4; u++) oacc[i][u] = 0ULL;

    __syncthreads();

    const float scale = 0.08838834764831845f;
    const float* adjbase = adj + ((size_t)b*LL + r0) * LL;

    for (int c0 = 0; c0 < LL; c0 += 64) {
        const float* kbase = g_qkv + ((size_t)(b*LL + c0)) * N3 + h*HD;
        for (int p = t; p < 64*32; p += 256) {
            int row = p >> 5, d4 = p & 31;
            const float* src = kbase + (size_t)row * N3 + d4*4;
            float4 kv = *(const float4*)src;
            float* kd = Ks + row*QS_STR + d4*4;
            kd[0]=kv.x; kd[1]=kv.y; kd[2]=kv.z; kd[3]=kv.w;
            *(float4*)(Vs + row*VS_STR + d4*4) = *(const float4*)(src + 2*CC);
        }
        for (int p = t; p < 64*16; p += 256) {
            int row = p >> 4, c4 = p & 15;
            float4 a = *(const float4*)(adjbase + (size_t)row * LL + c0 + c4*4);
            float* ad = Ssm + row*SS_STR + c4*4;
            ad[0]=a.x; ad[1]=a.y; ad[2]=a.z; ad[3]=a.w;
        }
        __syncthreads();

        float sacc[4][4];
        #pragma unroll
        for (int i = 0; i < 4; i++)
            #pragma unroll
            for (int j = 0; j < 4; j++) sacc[i][j] = 0.0f;
        for (int k = 0; k < HD; k++) {
            float qa[4], kb[4];
            #pragma unroll
            for (int i = 0; i < 4; i++) qa[i] = Qs[(rg*4+i)*QS_STR + k];
            #pragma unroll
            for (int j = 0; j < 4; j++) kb[j] = Ks[(cg*4+j)*QS_STR + k];
            #pragma unroll
            for (int i = 0; i < 4; i++)
                #pragma unroll
                for (int j = 0; j < 4; j++) sacc[i][j] += qa[i]*kb[j];
        }
        #pragma unroll
        for (int i = 0; i < 4; i++)
            #pragma unroll
            for (int j = 0; j < 4; j++) {
                float* cell = Ssm + (rg*4+i)*SS_STR + (cg*4+j);
                float a = *cell;
                *cell = (a != 0.0f) ? sacc[i][j]*scale : 0.0f;
            }
        __syncthreads();

        if (t < 64) {
            const float* row = Ssm + t*SS_STR;
            float s = 0.0f;
            #pragma unroll
            for (int c = 0; c < 64; c++) s += row[c];
            dsum[t] += s;
        }

        for (int k = 0; k < 64; k++) {
            float4 va = *(const float4*)(Vs + k*VS_STR + cg*8);
            float4 vb = *(const float4*)(Vs + k*VS_STR + cg*8 + 4);
            unsigned long long v2[4] = {pk(va.x,va.y), pk(va.z,va.w),
                                        pk(vb.x,vb.y), pk(vb.z,vb.w)};
            #pragma unroll
            for (int i = 0; i < 4; i++) {
                float s = Ssm[(rg*4+i)*SS_STR + k];
                unsigned long long s2 = pk(s, s);
                #pragma unroll
                for (int u = 0; u < 4; u++) ffma2(oacc[i][u], s2, v2[u]);
            }
        }
        __syncthreads();
    }

    #pragma unroll
    for (int i = 0; i < 4; i++) {
        int row = rg*4 + i;
        float inv = 1.0f / (dsum[row] + 1e-6f);
        const float* resp = g_qkv + ((size_t)(b*LL + r0 + row)) * N3 + CC + h*HD + cg*8;
        float4 rA = *(const float4*)resp;
        float4 rB = *(const float4*)(resp + 4);
        float o[8];
        upk(oacc[i][0], o[0], o[1]);
        upk(oacc[i][1], o[2], o[3]);
        upk(oacc[i][2], o[4], o[5]);
        upk(oacc[i][3], o[6], o[7]);
        float* dst = out + ((size_t)(b*LL + r0 + row)) * CC + h*HD + cg*8;
        *(float4*)dst = make_float4(
            fmaxf(o[0]*inv + rA.x, 0.0f), fmaxf(o[1]*inv + rA.y, 0.0f),
            fmaxf(o[2]*inv + rA.z, 0.0f), fmaxf(o[3]*inv + rA.w, 0.0f));
        *(float4*)(dst + 4) = make_float4(
            fmaxf(o[4]*inv + rB.x, 0.0f), fmaxf(o[5]*inv + rB.y, 0.0f),
            fmaxf(o[6]*inv + rB.z, 0.0f), fmaxf(o[7]*inv + rB.w, 0.0f));
    }
}

// ---------------------------------------------------------------------------
extern "C" void kernel_launch(void* const* d_in, const int* in_sizes, int n_in,
                              void* d_out, int out_size) {
    const float* x    = (const float*)d_in[0];
    const float* adj  = (const float*)d_in[1];
    const float* Wqkv = (const float*)d_in[2];
    const float* bqkv = (const float*)d_in[3];
    const float* Wd   = (const float*)d_in[4];
    const float* bd   = (const float*)d_in[5];
    float* out = (float*)d_out;

    cudaFuncSetAttribute(sgemm_mma,
                         cudaFuncAttributeMaxDynamicSharedMemorySize, SG_SMEM);
    cudaFuncSetAttribute(attn2_kernel,
                         cudaFuncAttributeMaxDynamicSharedMemorySize, ATTN_SMEM);

    degree_kernel<<<MM/8, 256>>>(adj);
    gate_kernel<<<(MM*CC/4)/256, 256>>>(x, Wd, bd);
    wprep_kernel<<<dim3(N3/32, CC/32), dim3(32, 8)>>>(Wqkv);
    sgemm_mma<<<dim3(N3/128, MM/128), 256, SG_SMEM>>>(bqkv);
    attn2_kernel<<<dim3(LL/64, NH*BB), 256, ATTN_SMEM>>>(adj, out);
}

// round 5
// speedup vs baseline: 5.8511x; 2.1106x over previous
#include <cuda_runtime.h>
#include <cuda_bf16.h>
#include <math.h>
#include <stdint.h>

#define BB 16
#define LL 512
#define CC 1024
#define NH 8
#define HD 128
#define MM (BB*LL)        // 8192 rows
#define N3 (3*CC)         // 3072
#define HM ((size_t)BB*NH*LL*HD)   // head-major elements = 8.39M

// Scratch (static device globals — no runtime allocation)
__device__ float g_deg[MM];
__device__ __nv_bfloat16 g_a_hi[(size_t)MM*CC];
__device__ __nv_bfloat16 g_a_lo[(size_t)MM*CC];
__device__ __nv_bfloat16 g_w_hi[(size_t)N3*CC];
__device__ __nv_bfloat16 g_w_lo[(size_t)N3*CC];
// head-major [bh][l][d] outputs of the projection
__device__ __nv_bfloat16 g_q_hi[HM];   // sig(qk) hi
__device__ __nv_bfloat16 g_q_lo[HM];
__device__ __nv_bfloat16 g_v_hi[HM];
__device__ __nv_bfloat16 g_v_lo[HM];
__device__ float g_res[HM];

__device__ __forceinline__ float sigmoidf(float v) {
    return 1.0f / (1.0f + expf(-v));
}

// ---------------- mma / async helpers (plain sm_80+ features) ----------------
__device__ __forceinline__ uint32_t smem_u32(const void* p) {
    return (uint32_t)__cvta_generic_to_shared((void*)p);
}
__device__ __forceinline__ void cp16(uint32_t dst, const void* src) {
    asm volatile("cp.async.cg.shared.global [%0], [%1], 16;" :: "r"(dst), "l"(src));
}
__device__ __forceinline__ void cp_commit() {
    asm volatile("cp.async.commit_group;" ::: "memory");
}
template<int N> __device__ __forceinline__ void cp_wait() {
    asm volatile("cp.async.wait_group %0;" :: "n"(N) : "memory");
}
__device__ __forceinline__ void ldm4(uint32_t* r, uint32_t addr) {
    asm volatile("ldmatrix.sync.aligned.m8n8.x4.shared.b16 {%0,%1,%2,%3},[%4];"
        : "=r"(r[0]), "=r"(r[1]), "=r"(r[2]), "=r"(r[3]) : "r"(addr));
}
__device__ __forceinline__ void ldm4t(uint32_t* r, uint32_t addr) {
    asm volatile("ldmatrix.sync.aligned.m8n8.x4.trans.shared.b16 {%0,%1,%2,%3},[%4];"
        : "=r"(r[0]), "=r"(r[1]), "=r"(r[2]), "=r"(r[3]) : "r"(addr));
}
__device__ __forceinline__ void mma16816(float* d, const uint32_t* a, const uint32_t* b) {
    asm volatile("mma.sync.aligned.m16n8k16.row.col.f32.bf16.bf16.f32 "
        "{%0,%1,%2,%3},{%4,%5,%6,%7},{%8,%9},{%0,%1,%2,%3};"
        : "+f"(d[0]), "+f"(d[1]), "+f"(d[2]), "+f"(d[3])
        : "r"(a[0]), "r"(a[1]), "r"(a[2]), "r"(a[3]), "r"(b[0]), "r"(b[1]));
}
__device__ __forceinline__ uint32_t bpack(__nv_bfloat16 a, __nv_bfloat16 b) {
    __nv_bfloat162 t = __halves2bfloat162(a, b);   // a -> low (even index)
    return *(uint32_t*)&t;
}
__device__ __forceinline__ void bsplit(float v, __nv_bfloat16& h, __nv_bfloat16& l) {
    h = __float2bfloat16(v);
    l = __float2bfloat16(v - __bfloat162float(h));
}

// ---------------------------------------------------------------------------
// K1: degree
// ---------------------------------------------------------------------------
__global__ void degree_kernel(const float* __restrict__ adj) {
    int warp = (blockIdx.x * blockDim.x + threadIdx.x) >> 5;
    int lane = threadIdx.x & 31;
    if (warp >= MM) return;
    const float4* row = (const float4*)(adj + (size_t)warp * LL);
    float s = 0.0f;
    #pragma unroll
    for (int j = 0; j < 4; j++) {
        float4 v = row[lane + 32*j];
        s += v.x + v.y + v.z + v.w;
    }
    #pragma unroll
    for (int o = 16; o > 0; o >>= 1) s += __shfl_xor_sync(0xffffffffu, s, o);
    if (lane == 0) g_deg[warp] = s;
}

// ---------------------------------------------------------------------------
// K2: gated x -> bf16 hi/lo split
// ---------------------------------------------------------------------------
__global__ void gate_kernel(const float* __restrict__ x,
                            const float* __restrict__ Wd,
                            const float* __restrict__ bd) {
    int i4 = blockIdx.x * blockDim.x + threadIdx.x;
    int row = i4 >> 8;
    int c4  = i4 & 255;
    float deg = g_deg[row];
    float4 xv = ((const float4*)x)[i4];
    float4 wv = ((const float4*)Wd)[c4];
    float4 bv = ((const float4*)bd)[c4];
    float v[4];
    v[0] = xv.x * sigmoidf(deg*wv.x + bv.x);
    v[1] = xv.y * sigmoidf(deg*wv.y + bv.y);
    v[2] = xv.z * sigmoidf(deg*wv.z + bv.z);
    v[3] = xv.w * sigmoidf(deg*wv.w + bv.w);
    __nv_bfloat16 h[4], l[4];
    #pragma unroll
    for (int j = 0; j < 4; j++) bsplit(v[j], h[j], l[j]);
    *(uint2*)&g_a_hi[(size_t)i4*4] = *(uint2*)h;
    *(uint2*)&g_a_lo[(size_t)i4*4] = *(uint2*)l;
}

// ---------------------------------------------------------------------------
// K2b: W[1024,3072] -> W^T[3072,1024] bf16 hi/lo
// ---------------------------------------------------------------------------
__global__ void wprep_kernel(const float* __restrict__ W) {
    __shared__ float t[32][33];
    int n0 = blockIdx.x * 32;
    int k0 = blockIdx.y * 32;
    int tx = threadIdx.x, ty = threadIdx.y;   // (32, 8)
    #pragma unroll
    for (int i = ty; i < 32; i += 8)
        t[i][tx] = W[(size_t)(k0 + i) * N3 + n0 + tx];
    __syncthreads();
    #pragma unroll
    for (int i = ty; i < 32; i += 8) {
        float v = t[tx][i];
        __nv_bfloat16 h, l;
        bsplit(v, h, l);
        size_t idx = (size_t)(n0 + i) * CC + k0 + tx;
        g_w_hi[idx] = h;
        g_w_lo[idx] = l;
    }
}

// ---------------------------------------------------------------------------
// K3: HMMA bf16-split GEMM; epilogue writes head-major q(sig,split)/res/v(split)
// ---------------------------------------------------------------------------
#define ROWB 80
#define TILE (128*ROWB)
#define STAGE (4*TILE)
#define SG_SMEM (2*STAGE)            // 80 KB

__global__ __launch_bounds__(256) void sgemm_mma(const float* __restrict__ bias) {
    extern __shared__ char sm[];
    uint32_t smb = smem_u32(sm);
    int tid = threadIdx.x, wid = tid >> 5, lane = tid & 31;
    int bx = blockIdx.x, by = blockIdx.y;
    int wm = wid & 3;
    int wn = wid >> 2;

    const __nv_bfloat16* Ah = g_a_hi + (size_t)by * 128 * CC;
    const __nv_bfloat16* Al = g_a_lo + (size_t)by * 128 * CC;
    const __nv_bfloat16* Bh = g_w_hi + (size_t)bx * 128 * CC;
    const __nv_bfloat16* Bl = g_w_lo + (size_t)bx * 128 * CC;

    float acc[2][8][4];
    #pragma unroll
    for (int t = 0; t < 2; t++)
        #pragma unroll
        for (int j = 0; j < 8; j++)
            #pragma unroll
            for (int u = 0; u < 4; u++) acc[t][j][u] = 0.0f;

    auto load_chunk = [&](int stage, int k0) {
        uint32_t base = smb + stage * STAGE;
        #pragma unroll
        for (int q = 0; q < 2; q++) {
            int c = tid + 256 * q;
            int row = c >> 2, s = c & 3;
            uint32_t off = (uint32_t)(row * ROWB + s * 16);
            size_t go = (size_t)row * CC + k0 + s * 8;
            cp16(base + off,            Ah + go);
            cp16(base + TILE + off,     Al + go);
            cp16(base + 2*TILE + off,   Bh + go);
            cp16(base + 3*TILE + off,   Bl + go);
        }
        cp_commit();
    };

    int li = lane >> 3, lr = lane & 7;
    int a_row = wm * 32 + (li & 1) * 8 + lr;
    int a_seg = li >> 1;
    int b_rowbase = wn * 64 + (li >> 1) * 8 + lr;
    int b_seg = li & 1;

    load_chunk(0, 0);

    #pragma unroll 1
    for (int i = 0; i < 32; i++) {
        cp_wait<0>();
        __syncthreads();
        if (i < 31) load_chunk((i + 1) & 1, (i + 1) * 32);

        uint32_t sb = smb + (i & 1) * STAGE;
        #pragma unroll
        for (int ks = 0; ks < 2; ks++) {
            uint32_t ah[2][4], al[2][4];
            #pragma unroll
            for (int t = 0; t < 2; t++) {
                uint32_t aoff = (uint32_t)((a_row + t*16) * ROWB + (ks*2 + a_seg) * 16);
                ldm4(ah[t], sb + aoff);
                ldm4(al[t], sb + TILE + aoff);
            }
            #pragma unroll
            for (int half = 0; half < 2; half++) {
                uint32_t bh[2][4], bl[2][4];
                #pragma unroll
                for (int bt = 0; bt < 2; bt++) {
                    uint32_t boff = (uint32_t)((b_rowbase + half*32 + bt*16) * ROWB
                                               + (ks*2 + b_seg) * 16);
                    ldm4(bh[bt], sb + 2*TILE + boff);
                    ldm4(bl[bt], sb + 3*TILE + boff);
                }
                #pragma unroll
                for (int t = 0; t < 2; t++) {
                    #pragma unroll
                    for (int j = 0; j < 4; j++) {
                        int jj = half * 4 + j;
                        const uint32_t* bhp = &bh[j >> 1][(j & 1) * 2];
                        const uint32_t* blp = &bl[j >> 1][(j & 1) * 2];
                        mma16816(acc[t][jj], ah[t], bhp);
                        mma16816(acc[t][jj], ah[t], blp);
                        mma16816(acc[t][jj], al[t], bhp);
                    }
                }
            }
        }
    }

    // epilogue -> head-major arrays
    int third = bx >> 3;          // 0=qk, 1=res, 2=value
    int head = bx & 7;
    #pragma unroll
    for (int t = 0; t < 2; t++) {
        int gr0 = by * 128 + wm * 32 + t * 16 + (lane >> 2);
        #pragma unroll
        for (int j = 0; j < 8; j++) {
            int col = wn * 64 + j * 8 + (lane & 3) * 2;
            float bx0 = bias[bx * 128 + col];
            float bx1 = bias[bx * 128 + col + 1];
            #pragma unroll
            for (int rsel = 0; rsel < 2; rsel++) {
                int gr = gr0 + rsel * 8;
                float v0 = acc[t][j][rsel*2 + 0] + bx0;
                float v1 = acc[t][j][rsel*2 + 1] + bx1;
                int b = gr >> 9, l = gr & 511;
                size_t idx = ((size_t)((b << 3) + head) * LL + l) * HD + col;
                if (third == 0) {
                    v0 = sigmoidf(v0); v1 = sigmoidf(v1);
                    __nv_bfloat16 h0,l0,h1,l1;
                    bsplit(v0,h0,l0); bsplit(v1,h1,l1);
                    *(uint32_t*)&g_q_hi[idx] = bpack(h0,h1);
                    *(uint32_t*)&g_q_lo[idx] = bpack(l0,l1);
                } else if (third == 1) {
                    *(float2*)&g_res[idx] = make_float2(v0, v1);
                } else {
                    __nv_bfloat16 h0,l0,h1,l1;
                    bsplit(v0,h0,l0); bsplit(v1,h1,l1);
                    *(uint32_t*)&g_v_hi[idx] = bpack(h0,h1);
                    *(uint32_t*)&g_v_lo[idx] = bpack(l0,l1);
                }
            }
        }
    }
}

// ---------------------------------------------------------------------------
// K4: HMMA attention. Block = 128 q-rows x one (b,h); 8 warps x 16 rows.
// 32-key chunks, double-buffered cp.async (K,V,adj). 3-term bf16 split.
// ---------------------------------------------------------------------------
#define QROWB 272
#define KROWB 272
#define ADJROWB 144
#define QTILE (128*QROWB)                    // 34816
#define KTILE (32*KROWB)                     // 8704
#define STAGEA (4*KTILE + 128*ADJROWB)       // 53248
#define AT_SMEM (2*QTILE + 2*STAGEA)         // 176128

__global__ __launch_bounds__(256, 1) void attn3_kernel(const float* __restrict__ adj,
                                                       float* __restrict__ out) {
    extern __shared__ char sm[];
    uint32_t smb = smem_u32(sm);
    int tid = threadIdx.x, warp = tid >> 5, lane = tid & 31;
    int li = lane >> 3, lr = lane & 7;
    int rt = blockIdx.x, bh = blockIdx.y;
    int b = bh >> 3, h = bh & 7;
    int r0 = rt * 128;
    int wr = warp * 16;

    const uint32_t QH = smb, QL = smb + QTILE;
    const float scale = 0.08838834764831845f;   // 1/sqrt(128)

    // load Q tile (both split arrays), rows r0..r0+127
    #pragma unroll
    for (int i = 0; i < 16; i++) {
        int idx = tid + 256 * i;
        int arr = idx >> 11, rem = idx & 2047;
        int row = rem >> 4, seg = rem & 15;
        const __nv_bfloat16* src = arr ? g_q_lo : g_q_hi;
        cp16(QH + arr*QTILE + (uint32_t)(row*QROWB + seg*16),
             src + ((size_t)bh*LL + r0 + row)*HD + seg*8);
    }
    cp_commit();

    auto load_stage = [&](int s, int c0) {
        uint32_t SB = smb + 2*QTILE + s*STAGEA;
        #pragma unroll
        for (int i = 0; i < 12; i++) {
            int idx = tid + 256 * i;
            if (idx < 2048) {
                int which = idx >> 10;            // 0=K (from q arrays), 1=V
                int arr = (idx >> 9) & 1;
                int rem = idx & 511;
                int row = rem >> 4, seg = rem & 15;
                const __nv_bfloat16* src =
                    which ? (arr ? g_v_lo : g_v_hi) : (arr ? g_q_lo : g_q_hi);
                cp16(SB + which*2*KTILE + arr*KTILE + (uint32_t)(row*KROWB + seg*16),
                     src + ((size_t)bh*LL + c0 + row)*HD + seg*8);
            } else {
                int rem = idx - 2048;
                int row = rem >> 3, g = rem & 7;
                cp16(SB + 4*KTILE + (uint32_t)(row*ADJROWB + g*16),
                     adj + ((size_t)(b*LL + r0 + row))*LL + c0 + g*4);
            }
        }
        cp_commit();
    };

    load_stage(0, 0);
    cp_wait<0>();
    __syncthreads();

    float Oacc[16][4];
    #pragma unroll
    for (int n = 0; n < 16; n++)
        #pragma unroll
        for (int u = 0; u < 4; u++) Oacc[n][u] = 0.0f;
    float d0 = 0.0f, d1 = 0.0f;

    #pragma unroll 1
    for (int c = 0; c < 16; c++) {
        if (c < 15) load_stage((c + 1) & 1, (c + 1) * 32);

        uint32_t SB = smb + 2*QTILE + (c & 1)*STAGEA;
        uint32_t KHB = SB, KLB = SB + KTILE, VHB = SB + 2*KTILE, VLB = SB + 3*KTILE;
        const float* adjs = (const float*)(sm + 2*QTILE + (c & 1)*STAGEA + 4*KTILE);

        // ---- phase 1: S[16,32] = Q·K^T (3-term) ----
        float S[4][4];
        #pragma unroll
        for (int j = 0; j < 4; j++)
            #pragma unroll
            for (int u = 0; u < 4; u++) S[j][u] = 0.0f;

        #pragma unroll
        for (int ks = 0; ks < 8; ks++) {
            uint32_t ah[4], al[4], kh[2][4], kl[2][4];
            uint32_t aoff = (uint32_t)((wr + (li&1)*8 + lr)*QROWB + ks*32 + (li>>1)*16);
            ldm4(ah, QH + aoff);
            ldm4(al, QL + aoff);
            #pragma unroll
            for (int g = 0; g < 2; g++) {
                uint32_t boff = (uint32_t)((g*16 + (li>>1)*8 + lr)*KROWB + ks*32 + (li&1)*16);
                ldm4(kh[g], KHB + boff);
                ldm4(kl[g], KLB + boff);
            }
            #pragma unroll
            for (int j = 0; j < 4; j++) {
                const uint32_t* ph = &kh[j>>1][(j&1)*2];
                const uint32_t* pl = &kl[j>>1][(j&1)*2];
                mma16816(S[j], ah, ph);
                mma16816(S[j], ah, pl);
                mma16816(S[j], al, ph);
            }
        }

        // ---- mask + scale + fp32 denom + split to A-fragments ----
        uint32_t Th[4][2], Tl[4][2];
        int ra = wr + (lane >> 2);
        #pragma unroll
        for (int j = 0; j < 4; j++) {
            int cb = j*8 + (lane & 3)*2;
            float a00 = adjs[ra*36 + cb],     a01 = adjs[ra*36 + cb + 1];
            float a10 = adjs[(ra+8)*36 + cb], a11 = adjs[(ra+8)*36 + cb + 1];
            float T00 = (a00 != 0.0f) ? S[j][0]*scale : 0.0f;
            float T01 = (a01 != 0.0f) ? S[j][1]*scale : 0.0f;
            float T10 = (a10 != 0.0f) ? S[j][2]*scale : 0.0f;
            float T11 = (a11 != 0.0f) ? S[j][3]*scale : 0.0f;
            d0 += T00 + T01;
            d1 += T10 + T11;
            __nv_bfloat16 h0,l0,h1,l1;
            bsplit(T00,h0,l0); bsplit(T01,h1,l1);
            Th[j][0] = bpack(h0,h1); Tl[j][0] = bpack(l0,l1);
            bsplit(T10,h0,l0); bsplit(T11,h1,l1);
            Th[j][1] = bpack(h0,h1); Tl[j][1] = bpack(l0,l1);
        }

        // ---- phase 2: O += T · V (3-term), V via ldmatrix.trans ----
        #pragma unroll
        for (int kk = 0; kk < 2; kk++) {
            uint32_t ahf[4] = {Th[2*kk][0], Th[2*kk][1], Th[2*kk+1][0], Th[2*kk+1][1]};
            uint32_t alf[4] = {Tl[2*kk][0], Tl[2*kk][1], Tl[2*kk+1][0], Tl[2*kk+1][1]};
            #pragma unroll
            for (int g = 0; g < 8; g++) {
                uint32_t bh4[4], bl4[4];
                uint32_t voff = (uint32_t)((kk*16 + (li&1)*8 + lr)*KROWB + g*32 + (li>>1)*16);
                ldm4t(bh4, VHB + voff);
                ldm4t(bl4, VLB + voff);
                #pragma unroll
                for (int j = 0; j < 2; j++) {
                    int nt = g*2 + j;
                    const uint32_t* pb = &bh4[j*2];
                    const uint32_t* pl = &bl4[j*2];
                    mma16816(Oacc[nt], ahf, pb);
                    mma16816(Oacc[nt], ahf, pl);
                    mma16816(Oacc[nt], alf, pb);
                }
            }
        }

        if (c < 15) cp_wait<0>();
        __syncthreads();
    }

    // ---- epilogue: reduce denom, normalize, +res, relu ----
    d0 += __shfl_xor_sync(0xffffffffu, d0, 1);
    d0 += __shfl_xor_sync(0xffffffffu, d0, 2);
    d1 += __shfl_xor_sync(0xffffffffu, d1, 1);
    d1 += __shfl_xor_sync(0xffffffffu, d1, 2);
    float inv0 = 1.0f / (d0 + 1e-6f);
    float inv1 = 1.0f / (d1 + 1e-6f);

    int gr0 = r0 + wr + (lane >> 2);
    #pragma unroll
    for (int nt = 0; nt < 16; nt++) {
        int col = nt*8 + (lane & 3)*2;
        size_t i0 = ((size_t)bh*LL + gr0)*HD + col;
        float2 rs0 = *(const float2*)(g_res + i0);
        float2 rs1 = *(const float2*)(g_res + i0 + 8*HD);
        float* o0 = out + ((size_t)(b*LL + gr0))*CC + h*HD + col;
        *(float2*)o0 = make_float2(
            fmaxf(Oacc[nt][0]*inv0 + rs0.x, 0.0f),
            fmaxf(Oacc[nt][1]*inv0 + rs0.y, 0.0f));
        *(float2*)(o0 + 8*CC) = make_float2(
            fmaxf(Oacc[nt][2]*inv1 + rs1.x, 0.0f),
            fmaxf(Oacc[nt][3]*inv1 + rs1.y, 0.0f));
    }
}

// ---------------------------------------------------------------------------
extern "C" void kernel_launch(void* const* d_in, const int* in_sizes, int n_in,
                              void* d_out, int out_size) {
    const float* x    = (const float*)d_in[0];
    const float* adj  = (const float*)d_in[1];
    const float* Wqkv = (const float*)d_in[2];
    const float* bqkv = (const float*)d_in[3];
    const float* Wd   = (const float*)d_in[4];
    const float* bd   = (const float*)d_in[5];
    float* out = (float*)d_out;

    cudaFuncSetAttribute(sgemm_mma,
                         cudaFuncAttributeMaxDynamicSharedMemorySize, SG_SMEM);
    cudaFuncSetAttribute(attn3_kernel,
                         cudaFuncAttributeMaxDynamicSharedMemorySize, AT_SMEM);

    degree_kernel<<<MM/8, 256>>>(adj);
    gate_kernel<<<(MM*CC/4)/256, 256>>>(x, Wd, bd);
    wprep_kernel<<<dim3(N3/32, CC/32), dim3(32, 8)>>>(Wqkv);
    sgemm_mma<<<dim3(N3/128, MM/128), 256, SG_SMEM>>>(bqkv);
    attn3_kernel<<<dim3(LL/128, NH*BB), 256, AT_SMEM>>>(adj, out);
}